// round 15
// baseline (speedup 1.0000x reference)
#include <cuda_runtime.h>
#include <math.h>
#include <stdint.h>

#define NB 4
#define NS 512
#define ND 1024
#define NH 16
#define NHD 64
#define NL 6
#define NF 4096
#define NV 32000
#define NT (NB*NS)   // 2048 tokens

#define SLAB_F ((size_t)12 * 1024 * 1024)  // floats: 4 DxD + DxF + FxD
#define O_WQ 0
#define O_WK ((size_t)1 * ND * ND)
#define O_WV ((size_t)2 * ND * ND)
#define O_WO ((size_t)3 * ND * ND)
#define O_W1 ((size_t)4 * ND * ND)
#define O_W2 ((size_t)8 * ND * ND)

// ---------------- scratch (device globals; no allocation) ----------------
__device__ float g_x  [NT*ND];
__device__ float g_q  [NT*ND];
__device__ float g_k  [NT*ND];
__device__ float g_v  [NT*ND];
__device__ float g_ctx[NT*ND];
__device__ float g_tmp[NT*ND];
__device__ float g_ff [NT*NF];
__device__ float g_slab[SLAB_F];           // per-layer transposed weights (48 MB)
__device__ float g_wtv [(size_t)NV * ND];  // Wout^T

// ---------------- small PTX helpers ----------------
__device__ __forceinline__ uint32_t smem_u32(const void* p) {
    uint32_t a;
    asm("{ .reg .u64 t; cvta.to.shared.u64 t, %1; cvt.u32.u64 %0, t; }" : "=r"(a) : "l"(p));
    return a;
}

#if defined(__CUDA_ARCH_FEAT_SM103_ALL)
__device__ __forceinline__ float to_tf32(float x) {
    uint32_t u = __float_as_uint(x), r;
    asm("cvt.rna.tf32.f32 %0, %1;" : "=r"(r) : "r"(u));
    return __uint_as_float(r);
}

#define MBAR_INIT(addr, cnt) \
    asm volatile("mbarrier.init.shared.b64 [%0], %1;" :: "r"(addr), "r"(cnt) : "memory")

#define MBAR_WAIT(addr, phase) do {                                               \
    uint32_t _m = (addr), _p = (phase), _d;                                       \
    asm volatile("{\n\t.reg .pred p;\n\t"                                         \
        "mbarrier.try_wait.parity.acquire.cta.shared::cta.b64 p, [%1], %2;\n\t"   \
        "selp.b32 %0, 1, 0, p;\n\t}" : "=r"(_d) : "r"(_m), "r"(_p) : "memory");   \
    while (!_d) {                                                                 \
        asm volatile("{\n\t.reg .pred p;\n\t"                                     \
            "mbarrier.try_wait.parity.acquire.cta.shared::cta.b64 p, [%1], %2, 0x989680;\n\t" \
            "selp.b32 %0, 1, 0, p;\n\t}" : "=r"(_d) : "r"(_m), "r"(_p) : "memory"); \
    }                                                                             \
} while (0)

#define TC_ALLOC(smem_addr, ncols) \
    asm volatile("tcgen05.alloc.cta_group::1.sync.aligned.shared::cta.b32 [%0], %1;" \
                 :: "r"(smem_addr), "r"(ncols) : "memory")
#define TC_RELINQ() \
    asm volatile("tcgen05.relinquish_alloc_permit.cta_group::1.sync.aligned;")
#define TC_DEALLOC(tmem, ncols) \
    asm volatile("tcgen05.dealloc.cta_group::1.sync.aligned.b32 %0, %1;" :: "r"(tmem), "r"(ncols))
#define TC_COMMIT(mbar) \
    asm volatile("tcgen05.commit.cta_group::1.mbarrier::arrive::one.shared::cluster.b64 [%0];" \
                 :: "r"(mbar) : "memory")
#define TC_FENCE_AFTER()  asm volatile("tcgen05.fence::after_thread_sync;" ::: "memory")
#define TC_FENCE_BEFORE() asm volatile("tcgen05.fence::before_thread_sync;" ::: "memory")
#define TC_WAIT_LD()      asm volatile("tcgen05.wait::ld.sync.aligned;" ::: "memory")

#define TC_LD32(r, addr)                                                      \
    asm volatile("tcgen05.ld.sync.aligned.32x32b.x32.b32 "                    \
        "{%0, %1, %2, %3, %4, %5, %6, %7, "                                   \
        " %8, %9, %10, %11, %12, %13, %14, %15, "                             \
        " %16, %17, %18, %19, %20, %21, %22, %23, "                           \
        " %24, %25, %26, %27, %28, %29, %30, %31}, [%32];"                    \
        : "=r"((r)[0]),  "=r"((r)[1]),  "=r"((r)[2]),  "=r"((r)[3]),          \
          "=r"((r)[4]),  "=r"((r)[5]),  "=r"((r)[6]),  "=r"((r)[7]),          \
          "=r"((r)[8]),  "=r"((r)[9]),  "=r"((r)[10]), "=r"((r)[11]),         \
          "=r"((r)[12]), "=r"((r)[13]), "=r"((r)[14]), "=r"((r)[15]),         \
          "=r"((r)[16]), "=r"((r)[17]), "=r"((r)[18]), "=r"((r)[19]),         \
          "=r"((r)[20]), "=r"((r)[21]), "=r"((r)[22]), "=r"((r)[23]),         \
          "=r"((r)[24]), "=r"((r)[25]), "=r"((r)[26]), "=r"((r)[27]),         \
          "=r"((r)[28]), "=r"((r)[29]), "=r"((r)[30]), "=r"((r)[31])          \
        : "r"(addr))

__device__ __forceinline__ void mma_tf32_ss(uint32_t d, uint64_t ad, uint64_t bd,
                                            uint32_t idesc, uint32_t en)
{
    asm volatile("{\n\t.reg .pred p;\n\tsetp.ne.u32 p, %4, 0;\n\t"
        "tcgen05.mma.cta_group::1.kind::tf32 [%0], %1, %2, %3, {%5, %5, %5, %5}, p;\n\t}"
        :: "r"(d), "l"(ad), "l"(bd), "r"(idesc), "r"(en), "r"(0u) : "memory");
}

// 64-bit smem matrix descriptor: K-major SW128, version=1, LBO=1, SBO=64
__device__ __forceinline__ uint64_t make_desc(uint32_t addr) {
    const uint64_t base = (uint64_t(2) << 61) | (uint64_t(1) << 46)
                        | (uint64_t(64) << 32) | (uint64_t(1) << 16);
    return base | ((uint64_t)(addr >> 4) & 0x3FFF);
}
#endif  // __CUDA_ARCH_FEAT_SM103_ALL

#define SWZ(bo) ((bo) ^ (((bo) >> 3) & 0x70))

// ---------------- weight transpose (R5 tile body) ----------------------------
__device__ __forceinline__ void
trans_tile(const float* __restrict__ in, float* __restrict__ out,
           int K, int N, int bx, int by)
{
    __shared__ float t[64][68];
    const int n0 = bx * 64, k0 = by * 64;
    const int tid = threadIdx.x;
#pragma unroll
    for (int i = 0; i < 4; i++) {
        int idx = tid + i * 256;
        int r = idx >> 4, c4 = (idx & 15) << 2;
        float4 v = *(const float4*)(in + (size_t)(k0 + r) * N + n0 + c4);
        t[c4 + 0][r] = v.x; t[c4 + 1][r] = v.y;
        t[c4 + 2][r] = v.z; t[c4 + 3][r] = v.w;
    }
    __syncthreads();
#pragma unroll
    for (int i = 0; i < 4; i++) {
        int idx = tid + i * 256;
        int r = idx >> 4, c4 = (idx & 15) << 2;
        float4 v;
        v.x = t[r][c4 + 0]; v.y = t[r][c4 + 1];
        v.z = t[r][c4 + 2]; v.w = t[r][c4 + 3];
        *(float4*)(out + (size_t)(n0 + r) * K + k0 + c4) = v;
    }
}

__global__ void __launch_bounds__(256)
transpose_kernel(const float* __restrict__ in, float* __restrict__ out, int K, int N)
{
    trans_tile(in, out, K, N, blockIdx.x, blockIdx.y);
}

// all 6 weights of one layer -> slab, one launch, 3072 CTAs (one tile each)
__global__ void __launch_bounds__(256)
trans6_kernel(const float* __restrict__ wq, const float* __restrict__ wk,
              const float* __restrict__ wv, const float* __restrict__ wo,
              const float* __restrict__ w1, const float* __restrict__ w2,
              float* __restrict__ slab)
{
    const int tt = blockIdx.x;
    const float* in; float* out; int K, N, bx, by;
    if (tt < 1024) {
        int w = tt >> 8, t = tt & 255;
        in  = (w == 0) ? wq : (w == 1) ? wk : (w == 2) ? wv : wo;
        out = slab + (size_t)w * ND * ND;
        K = ND; N = ND; bx = t & 15; by = t >> 4;
    } else if (tt < 2048) {
        int t = tt - 1024;
        in = w1; out = slab + O_W1;
        K = ND; N = NF; bx = t & 63; by = t >> 6;
    } else {
        int t = tt - 2048;
        in = w2; out = slab + O_W2;
        K = NF; N = ND; bx = t & 15; by = t >> 4;
    }
    trans_tile(in, out, K, N, bx, by);
}

// ---------------- GEMM (BN=128): EXACT R5 pipeline --------------------------
#define G_SMEM_BYTES 66560
#define G_IDESC ((1u<<4) | (2u<<7) | (2u<<10) | ((128u/8u)<<17) | ((128u/16u)<<24))

__global__ void __launch_bounds__(256)
gemm_tc(const float* __restrict__ A, const float* __restrict__ Bt,
        const float* __restrict__ bias, float* __restrict__ C,
        int M, int N, int K, int relu)
{
    extern __shared__ char smem[];
    const int tid = threadIdx.x;
    const int m0 = blockIdx.x * 128, n0 = blockIdx.y * 128;

#if defined(__CUDA_ARCH_FEAT_SM103_ALL)
    const uint32_t sb = smem_u32(smem);
    const uint32_t ab = (sb + 1023u) & ~1023u;
    const int wid = tid >> 5, lid = tid & 31;

    if (tid == 0) { MBAR_INIT(sb + 0, 1); MBAR_INIT(sb + 8, 1); }
    if (wid == 0) TC_ALLOC(sb + 16, 128u);
    __syncthreads();
    uint32_t tmem;
    asm volatile("ld.shared.b32 %0, [%1];" : "=r"(tmem) : "r"(sb + 16));

    char* smem_al = smem + (ab - sb);
    const int NC = K >> 5;                 // even (32 or 128)
    int ph0 = 0, ph1 = 0;

    const float* Ag = A  + (size_t)m0 * K;
    const float* Bg = Bt + (size_t)n0 * K;
    const int row_ = tid >> 3;             // 0..31 (+i*32)
    const int c4_  = (tid & 7) << 2;

    float4 ra[4], rb[4], na[4], nb[4];

#pragma unroll
    for (int i = 0; i < 4; i++) {
        int row = row_ + i * 32;
        ra[i] = *(const float4*)(Ag + (size_t)row * K + c4_);
        rb[i] = *(const float4*)(Bg + (size_t)row * K + c4_);
    }

    for (int c = 0; c < NC; c += 2) {
        if (c >= 2) { MBAR_WAIT(sb + 0, ph0); ph0 ^= 1; }
        {
            const int k0 = (c + 1) << 5;
#pragma unroll
            for (int i = 0; i < 4; i++) {
                int row = row_ + i * 32;
                na[i] = *(const float4*)(Ag + (size_t)row * K + k0 + c4_);
                nb[i] = *(const float4*)(Bg + (size_t)row * K + k0 + c4_);
            }
        }
        {
            char* As = smem_al;
            char* Bs = smem_al + 16384u;
            uint32_t bo0 = (uint32_t)(row_ * 128 + c4_ * 4);
#pragma unroll
            for (int i = 0; i < 4; i++) {
                uint32_t bo = SWZ(bo0 + (uint32_t)(i * 32 * 128));
                float4 va = ra[i];
                va.x = to_tf32(va.x); va.y = to_tf32(va.y);
                va.z = to_tf32(va.z); va.w = to_tf32(va.w);
                *(float4*)(As + bo) = va;
                float4 vb = rb[i];
                vb.x = to_tf32(vb.x); vb.y = to_tf32(vb.y);
                vb.z = to_tf32(vb.z); vb.w = to_tf32(vb.w);
                *(float4*)(Bs + bo) = vb;
            }
        }
        asm volatile("fence.proxy.async.shared::cta;" ::: "memory");
        __syncthreads();
        if (tid == 0) {
            uint64_t ad = make_desc(ab);
            uint64_t bd = make_desc(ab + 16384u);
#pragma unroll
            for (int ks = 0; ks < 4; ks++)
                mma_tf32_ss(tmem, ad + ks * 2, bd + ks * 2, G_IDESC,
                            (uint32_t)((c | ks) != 0));
            TC_COMMIT(sb + 0);
        }

        if (c + 1 >= 2) { MBAR_WAIT(sb + 8, ph1); ph1 ^= 1; }
        if (c + 2 < NC) {
            const int k0 = (c + 2) << 5;
#pragma unroll
            for (int i = 0; i < 4; i++) {
                int row = row_ + i * 32;
                ra[i] = *(const float4*)(Ag + (size_t)row * K + k0 + c4_);
                rb[i] = *(const float4*)(Bg + (size_t)row * K + k0 + c4_);
            }
        }
        {
            char* As = smem_al + 32768u;
            char* Bs = smem_al + 32768u + 16384u;
            uint32_t bo0 = (uint32_t)(row_ * 128 + c4_ * 4);
#pragma unroll
            for (int i = 0; i < 4; i++) {
                uint32_t bo = SWZ(bo0 + (uint32_t)(i * 32 * 128));
                float4 va = na[i];
                va.x = to_tf32(va.x); va.y = to_tf32(va.y);
                va.z = to_tf32(va.z); va.w = to_tf32(va.w);
                *(float4*)(As + bo) = va;
                float4 vb = nb[i];
                vb.x = to_tf32(vb.x); vb.y = to_tf32(vb.y);
                vb.z = to_tf32(vb.z); vb.w = to_tf32(vb.w);
                *(float4*)(Bs + bo) = vb;
            }
        }
        asm volatile("fence.proxy.async.shared::cta;" ::: "memory");
        __syncthreads();
        if (tid == 0) {
            uint64_t ad = make_desc(ab + 32768u);
            uint64_t bd = make_desc(ab + 32768u + 16384u);
#pragma unroll
            for (int ks = 0; ks < 4; ks++)
                mma_tf32_ss(tmem, ad + ks * 2, bd + ks * 2, G_IDESC, 1u);
            TC_COMMIT(sb + 8);
        }
    }
    MBAR_WAIT(sb + 0, ph0);
    MBAR_WAIT(sb + 8, ph1);
    TC_FENCE_AFTER();

    {
        const int wq = wid & 3, half = wid >> 2;
        uint32_t r[64];
        TC_LD32(r,      tmem + half * 64);
        TC_LD32(r + 32, tmem + half * 64 + 32);
        TC_WAIT_LD();
        TC_FENCE_BEFORE();
        const int m = m0 + wq * 32 + lid;
        const int nc0 = n0 + half * 64;
        float* Crow = C + (size_t)m * N + nc0;
        const float* brow = bias + nc0;
#pragma unroll
        for (int j = 0; j < 64; j += 4) {
            float4 bv = *(const float4*)(brow + j);
            float4 o;
            o.x = __uint_as_float(r[j + 0]) + bv.x;
            o.y = __uint_as_float(r[j + 1]) + bv.y;
            o.z = __uint_as_float(r[j + 2]) + bv.z;
            o.w = __uint_as_float(r[j + 3]) + bv.w;
            if (relu) {
                o.x = fmaxf(o.x, 0.f); o.y = fmaxf(o.y, 0.f);
                o.z = fmaxf(o.z, 0.f); o.w = fmaxf(o.w, 0.f);
            }
            *(float4*)(Crow + j) = o;
        }
    }
    __syncthreads();
    if (wid == 0) { TC_RELINQ(); TC_DEALLOC(tmem, 128u); }

#else
    // ======================= FFMA fallback (plain sm_103) ===================
    float (*As)[128] = (float(*)[128])smem;
    float (*Bs)[128] = (float(*)[128])(smem + 4096);
    const int tr = tid >> 4, tc = tid & 15;
    const int r_  = tid >> 1;
    const int c4f = (tid & 1) << 2;

    float acc[8][8];
#pragma unroll
    for (int i = 0; i < 8; i++)
#pragma unroll
        for (int j = 0; j < 8; j++) acc[i][j] = 0.0f;

    for (int k0 = 0; k0 < K; k0 += 8) {
        __syncthreads();
        float4 av = *(const float4*)(A  + (size_t)(m0 + r_) * K + k0 + c4f);
        As[c4f + 0][r_] = av.x; As[c4f + 1][r_] = av.y;
        As[c4f + 2][r_] = av.z; As[c4f + 3][r_] = av.w;
        float4 bv = *(const float4*)(Bt + (size_t)(n0 + r_) * K + k0 + c4f);
        Bs[c4f + 0][r_] = bv.x; Bs[c4f + 1][r_] = bv.y;
        Bs[c4f + 2][r_] = bv.z; Bs[c4f + 3][r_] = bv.w;
        __syncthreads();
#pragma unroll
        for (int kk = 0; kk < 8; kk++) {
            float a8[8], b8[8];
            *(float4*)&a8[0] = *(const float4*)&As[kk][tr * 8];
            *(float4*)&a8[4] = *(const float4*)&As[kk][tr * 8 + 4];
            *(float4*)&b8[0] = *(const float4*)&Bs[kk][tc * 8];
            *(float4*)&b8[4] = *(const float4*)&Bs[kk][tc * 8 + 4];
#pragma unroll
            for (int i = 0; i < 8; i++)
#pragma unroll
                for (int j = 0; j < 8; j++) acc[i][j] += a8[i] * b8[j];
        }
    }
#pragma unroll
    for (int i = 0; i < 8; i++) {
        size_t row = (size_t)(m0 + tr * 8 + i);
        int col0 = n0 + tc * 8;
#pragma unroll
        for (int jv = 0; jv < 2; jv++) {
            float4 o;
            o.x = acc[i][jv*4+0] + bias[col0 + jv*4 + 0];
            o.y = acc[i][jv*4+1] + bias[col0 + jv*4 + 1];
            o.z = acc[i][jv*4+2] + bias[col0 + jv*4 + 2];
            o.w = acc[i][jv*4+3] + bias[col0 + jv*4 + 3];
            if (relu) {
                o.x = fmaxf(o.x, 0.f); o.y = fmaxf(o.y, 0.f);
                o.z = fmaxf(o.z, 0.f); o.w = fmaxf(o.w, 0.f);
            }
            *(float4*)(C + row * N + col0 + jv * 4) = o;
        }
    }
#endif
}

// ---------------- embedding + sinusoidal PE ----------------
__global__ void __launch_bounds__(256)
embed_kernel(const int* __restrict__ ids, const float* __restrict__ emb,
             float* __restrict__ x)
{
    const int row = blockIdx.x;
    const int s   = row & (NS - 1);
    const int id  = ids[row];
    const float* er = emb + (size_t)id * ND;
    float* xr = x + (size_t)row * ND;
    const int tid = threadIdx.x;
#pragma unroll
    for (int i = 0; i < 4; i++) {
        int d  = tid + i * 256;
        int p2 = d & ~1;
        float freq = expf(-logf(10000.0f) * (float)p2 / (float)ND);
        float ang  = (float)s * freq;
        float pe   = (d & 1) ? cosf(ang) : sinf(ang);
        xr[d] = er[d] * 32.0f + pe;
    }
}

// ---------------- fused flash attention (R5 body) ----------------
#define FA_STR 65
#define FA_SMEM (4 * 64 * FA_STR * 4)

__global__ void __launch_bounds__(256)
flash_kernel(const float* __restrict__ q, const float* __restrict__ k,
             const float* __restrict__ v, const int* __restrict__ ids,
             float* __restrict__ ctx)
{
    extern __shared__ float fs[];
    float (*Qs)[FA_STR] = (float(*)[FA_STR])fs;
    float (*Ks)[FA_STR] = (float(*)[FA_STR])(fs + 64 * FA_STR);
    float (*Vs)[FA_STR] = (float(*)[FA_STR])(fs + 2 * 64 * FA_STR);
    float (*Ps)[FA_STR] = (float(*)[FA_STR])(fs + 3 * 64 * FA_STR);
    __shared__ int idt[64];

    const int qt = blockIdx.x;
    const int bh = blockIdx.y;
    const int b = bh >> 4, h = bh & 15;
    const int q0 = qt * 64;
    const int tid = threadIdx.x;
    const int tr = tid >> 4, tc = tid & 15;

    const float* qb = q + (size_t)b * NS * ND + h * NHD;
    const float* kb = k + (size_t)b * NS * ND + h * NHD;
    const float* vb = v + (size_t)b * NS * ND + h * NHD;
    const int* idr = ids + b * NS;

    for (int i = tid; i < 64 * 16; i += 256) {
        int r = i >> 4, c = (i & 15) << 2;
        float4 t = *(const float4*)(qb + (size_t)(q0 + r) * ND + c);
        Qs[r][c] = t.x; Qs[r][c+1] = t.y; Qs[r][c+2] = t.z; Qs[r][c+3] = t.w;
    }

    float m[4], l[4], O[4][4];
#pragma unroll
    for (int i = 0; i < 4; i++) {
        m[i] = -INFINITY; l[i] = 0.f;
#pragma unroll
        for (int j = 0; j < 4; j++) O[i][j] = 0.f;
    }

    for (int kt = 0; kt <= qt; kt++) {
        __syncthreads();
        for (int i = tid; i < 64 * 16; i += 256) {
            int r = i >> 4, c = (i & 15) << 2;
            float4 t = *(const float4*)(kb + (size_t)(kt * 64 + r) * ND + c);
            Ks[r][c] = t.x; Ks[r][c+1] = t.y; Ks[r][c+2] = t.z; Ks[r][c+3] = t.w;
            float4 u = *(const float4*)(vb + (size_t)(kt * 64 + r) * ND + c);
            Vs[r][c] = u.x; Vs[r][c+1] = u.y; Vs[r][c+2] = u.z; Vs[r][c+3] = u.w;
        }
        if (tid < 64) idt[tid] = idr[kt * 64 + tid];
        __syncthreads();

        float sc[4][4];
#pragma unroll
        for (int i = 0; i < 4; i++)
#pragma unroll
            for (int j = 0; j < 4; j++) sc[i][j] = 0.f;
#pragma unroll 16
        for (int d = 0; d < 64; d++) {
            float aq[4], ak[4];
#pragma unroll
            for (int i = 0; i < 4; i++) aq[i] = Qs[tr * 4 + i][d];
#pragma unroll
            for (int j = 0; j < 4; j++) ak[j] = Ks[tc * 4 + j][d];
#pragma unroll
            for (int i = 0; i < 4; i++)
#pragma unroll
                for (int j = 0; j < 4; j++) sc[i][j] += aq[i] * ak[j];
        }
#pragma unroll
        for (int i = 0; i < 4; i++) {
            int qq = q0 + tr * 4 + i;
#pragma unroll
            for (int j = 0; j < 4; j++) {
                int kk = kt * 64 + tc * 4 + j;
                bool masked = (kk > qq) || (idt[tc * 4 + j] == 0);
                sc[i][j] = masked ? -INFINITY : sc[i][j] * 0.125f;
            }
        }
#pragma unroll
        for (int i = 0; i < 4; i++) {
            float tmax = fmaxf(fmaxf(sc[i][0], sc[i][1]), fmaxf(sc[i][2], sc[i][3]));
#pragma unroll
            for (int o = 8; o > 0; o >>= 1)
                tmax = fmaxf(tmax, __shfl_xor_sync(0xffffffffu, tmax, o));
            float mn = fmaxf(m[i], tmax);
            float alpha = (m[i] == -INFINITY) ? 0.f : expf(m[i] - mn);
            float p0 = (sc[i][0] == -INFINITY) ? 0.f : expf(sc[i][0] - mn);
            float p1 = (sc[i][1] == -INFINITY) ? 0.f : expf(sc[i][1] - mn);
            float p2 = (sc[i][2] == -INFINITY) ? 0.f : expf(sc[i][2] - mn);
            float p3 = (sc[i][3] == -INFINITY) ? 0.f : expf(sc[i][3] - mn);
            float rsum = p0 + p1 + p2 + p3;
#pragma unroll
            for (int o = 8; o > 0; o >>= 1)
                rsum += __shfl_xor_sync(0xffffffffu, rsum, o);
            l[i] = l[i] * alpha + rsum;
            m[i] = mn;
            Ps[tr * 4 + i][tc * 4 + 0] = p0;
            Ps[tr * 4 + i][tc * 4 + 1] = p1;
            Ps[tr * 4 + i][tc * 4 + 2] = p2;
            Ps[tr * 4 + i][tc * 4 + 3] = p3;
#pragma unroll
            for (int j = 0; j < 4; j++) O[i][j] *= alpha;
        }
        __syncthreads();
#pragma unroll 16
        for (int d = 0; d < 64; d++) {
            float ap[4], av4[4];
#pragma unroll
            for (int i = 0; i < 4; i++) ap[i] = Ps[tr * 4 + i][d];
#pragma unroll
            for (int j = 0; j < 4; j++) av4[j] = Vs[d][tc * 4 + j];
#pragma unroll
            for (int i = 0; i < 4; i++)
#pragma unroll
                for (int j = 0; j < 4; j++) O[i][j] += ap[i] * av4[j];
        }
    }

#pragma unroll
    for (int i = 0; i < 4; i++) {
        int qq = q0 + tr * 4 + i;
        float4 o;
        if (m[i] == -INFINITY) {
            float s0 = 0.f, s1 = 0.f, s2 = 0.f, s3 = 0.f;
            for (int kk = 0; kk < NS; kk++) {
                const float* vr = vb + (size_t)kk * ND + tc * 4;
                s0 += vr[0]; s1 += vr[1]; s2 += vr[2]; s3 += vr[3];
            }
            o.x = s0 * (1.0f / NS); o.y = s1 * (1.0f / NS);
            o.z = s2 * (1.0f / NS); o.w = s3 * (1.0f / NS);
        } else {
            float inv = 1.0f / l[i];
            o.x = O[i][0] * inv; o.y = O[i][1] * inv;
            o.z = O[i][2] * inv; o.w = O[i][3] * inv;
        }
        *(float4*)(ctx + (size_t)(b * NS + qq) * ND + h * NHD + tc * 4) = o;
    }
}

// ---------------- x = LayerNorm(x + y) ----------------
__global__ void __launch_bounds__(256)
ln_kernel(float* __restrict__ x, const float* __restrict__ y,
          const float* __restrict__ g, const float* __restrict__ b)
{
    const int row = blockIdx.x;
    float* xr = x + (size_t)row * ND;
    const float* yr = y + (size_t)row * ND;
    const int tid = threadIdx.x;
    float4 xv = *(float4*)(xr + tid * 4);
    float4 yv = *(const float4*)(yr + tid * 4);
    float t0 = xv.x + yv.x, t1 = xv.y + yv.y, t2 = xv.z + yv.z, t3 = xv.w + yv.w;
    float s  = t0 + t1 + t2 + t3;
    float ss = t0*t0 + t1*t1 + t2*t2 + t3*t3;
#pragma unroll
    for (int o = 16; o > 0; o >>= 1) {
        s  += __shfl_xor_sync(0xffffffffu, s,  o);
        ss += __shfl_xor_sync(0xffffffffu, ss, o);
    }
    __shared__ float rs[8], rss[8];
    if ((tid & 31) == 0) { rs[tid >> 5] = s; rss[tid >> 5] = ss; }
    __syncthreads();
    float S = 0.f, SS = 0.f;
#pragma unroll
    for (int w = 0; w < 8; w++) { S += rs[w]; SS += rss[w]; }
    float mean = S * (1.0f / ND);
    float var  = SS * (1.0f / ND) - mean * mean;
    float rstd = rsqrtf(var + 1e-5f);
    float4 gv = *(const float4*)(g + tid * 4);
    float4 bv = *(const float4*)(b + tid * 4);
    float4 o;
    o.x = (t0 - mean) * rstd * gv.x + bv.x;
    o.y = (t1 - mean) * rstd * gv.y + bv.y;
    o.z = (t2 - mean) * rstd * gv.z + bv.z;
    o.w = (t3 - mean) * rstd * gv.w + bv.w;
    *(float4*)(xr + tid * 4) = o;
}

// ---------------- host orchestration (single stream, R5 order) --------------
extern "C" void kernel_launch(void* const* d_in, const int* in_sizes, int n_in,
                              void* d_out, int out_size)
{
    const int*   ids  = (const int*)  d_in[0];
    const float* emb  = (const float*)d_in[2];
    const float* Wq   = (const float*)d_in[3];
    const float* bq   = (const float*)d_in[4];
    const float* Wk   = (const float*)d_in[5];
    const float* bk   = (const float*)d_in[6];
    const float* Wv   = (const float*)d_in[7];
    const float* bv   = (const float*)d_in[8];
    const float* Wo   = (const float*)d_in[9];
    const float* bo   = (const float*)d_in[10];
    const float* g1   = (const float*)d_in[11];
    const float* b1n  = (const float*)d_in[12];
    const float* W1   = (const float*)d_in[13];
    const float* b1f  = (const float*)d_in[14];
    const float* W2   = (const float*)d_in[15];
    const float* b2f  = (const float*)d_in[16];
    const float* g2   = (const float*)d_in[17];
    const float* b2n  = (const float*)d_in[18];
    const float* Wout = (const float*)d_in[19];
    const float* bout = (const float*)d_in[20];
    float* out = (float*)d_out;

    float *px, *pq, *pk, *pv, *pctx, *ptmp, *pff, *pslab, *pwtv;
    cudaGetSymbolAddress((void**)&px,    g_x);
    cudaGetSymbolAddress((void**)&pq,    g_q);
    cudaGetSymbolAddress((void**)&pk,    g_k);
    cudaGetSymbolAddress((void**)&pv,    g_v);
    cudaGetSymbolAddress((void**)&pctx,  g_ctx);
    cudaGetSymbolAddress((void**)&ptmp,  g_tmp);
    cudaGetSymbolAddress((void**)&pff,   g_ff);
    cudaGetSymbolAddress((void**)&pslab, g_slab);
    cudaGetSymbolAddress((void**)&pwtv,  g_wtv);

    cudaFuncSetAttribute(gemm_tc, cudaFuncAttributeMaxDynamicSharedMemorySize,
                         G_SMEM_BYTES);
    cudaFuncSetAttribute(flash_kernel, cudaFuncAttributeMaxDynamicSharedMemorySize,
                         FA_SMEM);

    embed_kernel<<<NT, 256>>>(ids, emb, px);

    const dim3 tDV(NV / 64, ND / 64);         // (500,16) Wout transpose

    const dim3 gProj(NT / 128, ND / 128);     // (16, 8)
    const dim3 gFF1 (NT / 128, NF / 128);     // (16, 32)
    const dim3 gOut (NT / 128, NV / 128);     // (16, 250)
    const dim3 gFA  (NS / 64, NB * NH);       // (8, 64)

    for (int l = 0; l < NL; l++) {
        // one launch: all 6 weight transposes of this layer (3072 CTAs)
        trans6_kernel<<<3072, 256>>>(Wq + (size_t)l * ND * ND,
                                     Wk + (size_t)l * ND * ND,
                                     Wv + (size_t)l * ND * ND,
                                     Wo + (size_t)l * ND * ND,
                                     W1 + (size_t)l * ND * NF,
                                     W2 + (size_t)l * NF * ND, pslab);

        gemm_tc<<<gProj, 256, G_SMEM_BYTES>>>(px, pslab + O_WQ,
                                              bq + l * ND, pq, NT, ND, ND, 0);
        gemm_tc<<<gProj, 256, G_SMEM_BYTES>>>(px, pslab + O_WK,
                                              bk + l * ND, pk, NT, ND, ND, 0);
        gemm_tc<<<gProj, 256, G_SMEM_BYTES>>>(px, pslab + O_WV,
                                              bv + l * ND, pv, NT, ND, ND, 0);

        flash_kernel<<<gFA, 256, FA_SMEM>>>(pq, pk, pv, ids, pctx);

        gemm_tc<<<gProj, 256, G_SMEM_BYTES>>>(pctx, pslab + O_WO,
                                              bo + l * ND, ptmp, NT, ND, ND, 0);
        ln_kernel<<<NT, 256>>>(px, ptmp, g1 + l * ND, b1n + l * ND);

        gemm_tc<<<gFF1, 256, G_SMEM_BYTES>>>(px, pslab + O_W1,
                                             b1f + l * NF, pff, NT, NF, ND, 1);
        gemm_tc<<<gProj, 256, G_SMEM_BYTES>>>(pff, pslab + O_W2,
                                              b2f + l * ND, ptmp, NT, ND, NF, 0);
        ln_kernel<<<NT, 256>>>(px, ptmp, g2 + l * ND, b2n + l * ND);
    }

    transpose_kernel<<<tDV, 256>>>(Wout, pwtv, ND, NV);
    gemm_tc<<<gOut, 256, G_SMEM_BYTES>>>(px, pwtv, bout, out, NT, NV, ND, 0);
}

// round 16
// speedup vs baseline: 1.1259x; 1.1259x over previous
#include <cuda_runtime.h>
#include <math.h>
#include <stdint.h>

#define NB 4
#define NS 512
#define ND 1024
#define NH 16
#define NHD 64
#define NL 6
#define NF 4096
#define NV 32000
#define NT (NB*NS)   // 2048 tokens

// ---------------- scratch (device globals; no allocation) ----------------
__device__ float g_x  [NT*ND];
__device__ float g_q  [NT*ND];
__device__ float g_k  [NT*ND];
__device__ float g_v  [NT*ND];
__device__ float g_ctx[NT*ND];
__device__ float g_tmp[NT*ND];
__device__ float g_ff [NT*NF];
__device__ float g_wt [(size_t)NV*ND];   // transposed-weight buffer

// ---------------- small PTX helpers ----------------
__device__ __forceinline__ uint32_t smem_u32(const void* p) {
    uint32_t a;
    asm("{ .reg .u64 t; cvta.to.shared.u64 t, %1; cvt.u32.u64 %0, t; }" : "=r"(a) : "l"(p));
    return a;
}

#if defined(__CUDA_ARCH_FEAT_SM103_ALL)
__device__ __forceinline__ float to_tf32(float x) {
    uint32_t u = __float_as_uint(x), r;
    asm("cvt.rna.tf32.f32 %0, %1;" : "=r"(r) : "r"(u));
    return __uint_as_float(r);
}

#define MBAR_INIT(addr, cnt) \
    asm volatile("mbarrier.init.shared.b64 [%0], %1;" :: "r"(addr), "r"(cnt) : "memory")

#define MBAR_WAIT(addr, phase) do {                                               \
    uint32_t _m = (addr), _p = (phase), _d;                                       \
    asm volatile("{\n\t.reg .pred p;\n\t"                                         \
        "mbarrier.try_wait.parity.acquire.cta.shared::cta.b64 p, [%1], %2;\n\t"   \
        "selp.b32 %0, 1, 0, p;\n\t}" : "=r"(_d) : "r"(_m), "r"(_p) : "memory");   \
    while (!_d) {                                                                 \
        asm volatile("{\n\t.reg .pred p;\n\t"                                     \
            "mbarrier.try_wait.parity.acquire.cta.shared::cta.b64 p, [%1], %2, 0x989680;\n\t" \
            "selp.b32 %0, 1, 0, p;\n\t}" : "=r"(_d) : "r"(_m), "r"(_p) : "memory"); \
    }                                                                             \
} while (0)

#define TC_ALLOC(smem_addr, ncols) \
    asm volatile("tcgen05.alloc.cta_group::1.sync.aligned.shared::cta.b32 [%0], %1;" \
                 :: "r"(smem_addr), "r"(ncols) : "memory")
#define TC_RELINQ() \
    asm volatile("tcgen05.relinquish_alloc_permit.cta_group::1.sync.aligned;")
#define TC_DEALLOC(tmem, ncols) \
    asm volatile("tcgen05.dealloc.cta_group::1.sync.aligned.b32 %0, %1;" :: "r"(tmem), "r"(ncols))
#define TC_COMMIT(mbar) \
    asm volatile("tcgen05.commit.cta_group::1.mbarrier::arrive::one.shared::cluster.b64 [%0];" \
                 :: "r"(mbar) : "memory")
#define TC_FENCE_AFTER()  asm volatile("tcgen05.fence::after_thread_sync;" ::: "memory")
#define TC_FENCE_BEFORE() asm volatile("tcgen05.fence::before_thread_sync;" ::: "memory")
#define TC_WAIT_LD()      asm volatile("tcgen05.wait::ld.sync.aligned;" ::: "memory")

#define TC_LD32(r, addr)                                                      \
    asm volatile("tcgen05.ld.sync.aligned.32x32b.x32.b32 "                    \
        "{%0, %1, %2, %3, %4, %5, %6, %7, "                                   \
        " %8, %9, %10, %11, %12, %13, %14, %15, "                             \
        " %16, %17, %18, %19, %20, %21, %22, %23, "                           \
        " %24, %25, %26, %27, %28, %29, %30, %31}, [%32];"                    \
        : "=r"((r)[0]),  "=r"((r)[1]),  "=r"((r)[2]),  "=r"((r)[3]),          \
          "=r"((r)[4]),  "=r"((r)[5]),  "=r"((r)[6]),  "=r"((r)[7]),          \
          "=r"((r)[8]),  "=r"((r)[9]),  "=r"((r)[10]), "=r"((r)[11]),         \
          "=r"((r)[12]), "=r"((r)[13]), "=r"((r)[14]), "=r"((r)[15]),         \
          "=r"((r)[16]), "=r"((r)[17]), "=r"((r)[18]), "=r"((r)[19]),         \
          "=r"((r)[20]), "=r"((r)[21]), "=r"((r)[22]), "=r"((r)[23]),         \
          "=r"((r)[24]), "=r"((r)[25]), "=r"((r)[26]), "=r"((r)[27]),         \
          "=r"((r)[28]), "=r"((r)[29]), "=r"((r)[30]), "=r"((r)[31])          \
        : "r"(addr))

__device__ __forceinline__ void mma_tf32_ss(uint32_t d, uint64_t ad, uint64_t bd,
                                            uint32_t idesc, uint32_t en)
{
    asm volatile("{\n\t.reg .pred p;\n\tsetp.ne.u32 p, %4, 0;\n\t"
        "tcgen05.mma.cta_group::1.kind::tf32 [%0], %1, %2, %3, {%5, %5, %5, %5}, p;\n\t}"
        :: "r"(d), "l"(ad), "l"(bd), "r"(idesc), "r"(en), "r"(0u) : "memory");
}

// 64-bit smem matrix descriptor: K-major SW128, version=1, LBO=1, SBO=64
__device__ __forceinline__ uint64_t make_desc(uint32_t addr) {
    const uint64_t base = (uint64_t(2) << 61) | (uint64_t(1) << 46)
                        | (uint64_t(64) << 32) | (uint64_t(1) << 16);
    return base | ((uint64_t)(addr >> 4) & 0x3FFF);
}
#endif  // __CUDA_ARCH_FEAT_SM103_ALL

#define SWZ(bo) ((bo) ^ (((bo) >> 3) & 0x70))

// ---------------- weight transpose: out[n][k] = in[k][n] (R5 body) ----------
__global__ void __launch_bounds__(256)
transpose_kernel(const float* __restrict__ in, float* __restrict__ out, int K, int N)
{
    __shared__ float t[64][68];
    const int n0 = blockIdx.x * 64, k0 = blockIdx.y * 64;
    const int tid = threadIdx.x;
#pragma unroll
    for (int i = 0; i < 4; i++) {
        int idx = tid + i * 256;
        int r = idx >> 4, c4 = (idx & 15) << 2;
        float4 v = *(const float4*)(in + (size_t)(k0 + r) * N + n0 + c4);
        t[c4 + 0][r] = v.x; t[c4 + 1][r] = v.y;
        t[c4 + 2][r] = v.z; t[c4 + 3][r] = v.w;
    }
    __syncthreads();
#pragma unroll
    for (int i = 0; i < 4; i++) {
        int idx = tid + i * 256;
        int r = idx >> 4, c4 = (idx & 15) << 2;
        float4 v;
        v.x = t[r][c4 + 0]; v.y = t[r][c4 + 1];
        v.z = t[r][c4 + 2]; v.w = t[r][c4 + 3];
        *(float4*)(out + (size_t)(n0 + r) * K + k0 + c4) = v;
    }
}

// ---------------- GEMM (BN=128): EXACT R5 pipeline --------------------------
#define G_SMEM_BYTES 66560
#define G_IDESC ((1u<<4) | (2u<<7) | (2u<<10) | ((128u/8u)<<17) | ((128u/16u)<<24))

__global__ void __launch_bounds__(256)
gemm_tc(const float* __restrict__ A, const float* __restrict__ Bt,
        const float* __restrict__ bias, float* __restrict__ C,
        int M, int N, int K, int relu)
{
    extern __shared__ char smem[];
    const int tid = threadIdx.x;
    const int m0 = blockIdx.x * 128, n0 = blockIdx.y * 128;

#if defined(__CUDA_ARCH_FEAT_SM103_ALL)
    const uint32_t sb = smem_u32(smem);
    const uint32_t ab = (sb + 1023u) & ~1023u;
    const int wid = tid >> 5, lid = tid & 31;

    if (tid == 0) { MBAR_INIT(sb + 0, 1); MBAR_INIT(sb + 8, 1); }
    if (wid == 0) TC_ALLOC(sb + 16, 128u);
    __syncthreads();
    uint32_t tmem;
    asm volatile("ld.shared.b32 %0, [%1];" : "=r"(tmem) : "r"(sb + 16));

    char* smem_al = smem + (ab - sb);
    const int NC = K >> 5;                 // even (32 or 128)
    int ph0 = 0, ph1 = 0;

    const float* Ag = A  + (size_t)m0 * K;
    const float* Bg = Bt + (size_t)n0 * K;
    const int row_ = tid >> 3;             // 0..31 (+i*32)
    const int c4_  = (tid & 7) << 2;

    float4 ra[4], rb[4], na[4], nb[4];

#pragma unroll
    for (int i = 0; i < 4; i++) {
        int row = row_ + i * 32;
        ra[i] = *(const float4*)(Ag + (size_t)row * K + c4_);
        rb[i] = *(const float4*)(Bg + (size_t)row * K + c4_);
    }

    for (int c = 0; c < NC; c += 2) {
        if (c >= 2) { MBAR_WAIT(sb + 0, ph0); ph0 ^= 1; }
        {
            const int k0 = (c + 1) << 5;
#pragma unroll
            for (int i = 0; i < 4; i++) {
                int row = row_ + i * 32;
                na[i] = *(const float4*)(Ag + (size_t)row * K + k0 + c4_);
                nb[i] = *(const float4*)(Bg + (size_t)row * K + k0 + c4_);
            }
        }
        {
            char* As = smem_al;
            char* Bs = smem_al + 16384u;
            uint32_t bo0 = (uint32_t)(row_ * 128 + c4_ * 4);
#pragma unroll
            for (int i = 0; i < 4; i++) {
                uint32_t bo = SWZ(bo0 + (uint32_t)(i * 32 * 128));
                float4 va = ra[i];
                va.x = to_tf32(va.x); va.y = to_tf32(va.y);
                va.z = to_tf32(va.z); va.w = to_tf32(va.w);
                *(float4*)(As + bo) = va;
                float4 vb = rb[i];
                vb.x = to_tf32(vb.x); vb.y = to_tf32(vb.y);
                vb.z = to_tf32(vb.z); vb.w = to_tf32(vb.w);
                *(float4*)(Bs + bo) = vb;
            }
        }
        asm volatile("fence.proxy.async.shared::cta;" ::: "memory");
        __syncthreads();
        if (tid == 0) {
            uint64_t ad = make_desc(ab);
            uint64_t bd = make_desc(ab + 16384u);
#pragma unroll
            for (int ks = 0; ks < 4; ks++)
                mma_tf32_ss(tmem, ad + ks * 2, bd + ks * 2, G_IDESC,
                            (uint32_t)((c | ks) != 0));
            TC_COMMIT(sb + 0);
        }

        if (c + 1 >= 2) { MBAR_WAIT(sb + 8, ph1); ph1 ^= 1; }
        if (c + 2 < NC) {
            const int k0 = (c + 2) << 5;
#pragma unroll
            for (int i = 0; i < 4; i++) {
                int row = row_ + i * 32;
                ra[i] = *(const float4*)(Ag + (size_t)row * K + k0 + c4_);
                rb[i] = *(const float4*)(Bg + (size_t)row * K + k0 + c4_);
            }
        }
        {
            char* As = smem_al + 32768u;
            char* Bs = smem_al + 32768u + 16384u;
            uint32_t bo0 = (uint32_t)(row_ * 128 + c4_ * 4);
#pragma unroll
            for (int i = 0; i < 4; i++) {
                uint32_t bo = SWZ(bo0 + (uint32_t)(i * 32 * 128));
                float4 va = na[i];
                va.x = to_tf32(va.x); va.y = to_tf32(va.y);
                va.z = to_tf32(va.z); va.w = to_tf32(va.w);
                *(float4*)(As + bo) = va;
                float4 vb = nb[i];
                vb.x = to_tf32(vb.x); vb.y = to_tf32(vb.y);
                vb.z = to_tf32(vb.z); vb.w = to_tf32(vb.w);
                *(float4*)(Bs + bo) = vb;
            }
        }
        asm volatile("fence.proxy.async.shared::cta;" ::: "memory");
        __syncthreads();
        if (tid == 0) {
            uint64_t ad = make_desc(ab + 32768u);
            uint64_t bd = make_desc(ab + 32768u + 16384u);
#pragma unroll
            for (int ks = 0; ks < 4; ks++)
                mma_tf32_ss(tmem, ad + ks * 2, bd + ks * 2, G_IDESC, 1u);
            TC_COMMIT(sb + 8);
        }
    }
    MBAR_WAIT(sb + 0, ph0);
    MBAR_WAIT(sb + 8, ph1);
    TC_FENCE_AFTER();

    {
        const int wq = wid & 3, half = wid >> 2;
        uint32_t r[64];
        TC_LD32(r,      tmem + half * 64);
        TC_LD32(r + 32, tmem + half * 64 + 32);
        TC_WAIT_LD();
        TC_FENCE_BEFORE();
        const int m = m0 + wq * 32 + lid;
        const int nc0 = n0 + half * 64;
        float* Crow = C + (size_t)m * N + nc0;
        const float* brow = bias + nc0;
#pragma unroll
        for (int j = 0; j < 64; j += 4) {
            float4 bv = *(const float4*)(brow + j);
            float4 o;
            o.x = __uint_as_float(r[j + 0]) + bv.x;
            o.y = __uint_as_float(r[j + 1]) + bv.y;
            o.z = __uint_as_float(r[j + 2]) + bv.z;
            o.w = __uint_as_float(r[j + 3]) + bv.w;
            if (relu) {
                o.x = fmaxf(o.x, 0.f); o.y = fmaxf(o.y, 0.f);
                o.z = fmaxf(o.z, 0.f); o.w = fmaxf(o.w, 0.f);
            }
            *(float4*)(Crow + j) = o;
        }
    }
    __syncthreads();
    if (wid == 0) { TC_RELINQ(); TC_DEALLOC(tmem, 128u); }

#else
    // ======================= FFMA fallback (plain sm_103) ===================
    float (*As)[128] = (float(*)[128])smem;
    float (*Bs)[128] = (float(*)[128])(smem + 4096);
    const int tr = tid >> 4, tc = tid & 15;
    const int r_  = tid >> 1;
    const int c4f = (tid & 1) << 2;

    float acc[8][8];
#pragma unroll
    for (int i = 0; i < 8; i++)
#pragma unroll
        for (int j = 0; j < 8; j++) acc[i][j] = 0.0f;

    for (int k0 = 0; k0 < K; k0 += 8) {
        __syncthreads();
        float4 av = *(const float4*)(A  + (size_t)(m0 + r_) * K + k0 + c4f);
        As[c4f + 0][r_] = av.x; As[c4f + 1][r_] = av.y;
        As[c4f + 2][r_] = av.z; As[c4f + 3][r_] = av.w;
        float4 bv = *(const float4*)(Bt + (size_t)(n0 + r_) * K + k0 + c4f);
        Bs[c4f + 0][r_] = bv.x; Bs[c4f + 1][r_] = bv.y;
        Bs[c4f + 2][r_] = bv.z; Bs[c4f + 3][r_] = bv.w;
        __syncthreads();
#pragma unroll
        for (int kk = 0; kk < 8; kk++) {
            float a8[8], b8[8];
            *(float4*)&a8[0] = *(const float4*)&As[kk][tr * 8];
            *(float4*)&a8[4] = *(const float4*)&As[kk][tr * 8 + 4];
            *(float4*)&b8[0] = *(const float4*)&Bs[kk][tc * 8];
            *(float4*)&b8[4] = *(const float4*)&Bs[kk][tc * 8 + 4];
#pragma unroll
            for (int i = 0; i < 8; i++)
#pragma unroll
                for (int j = 0; j < 8; j++) acc[i][j] += a8[i] * b8[j];
        }
    }
#pragma unroll
    for (int i = 0; i < 8; i++) {
        size_t row = (size_t)(m0 + tr * 8 + i);
        int col0 = n0 + tc * 8;
#pragma unroll
        for (int jv = 0; jv < 2; jv++) {
            float4 o;
            o.x = acc[i][jv*4+0] + bias[col0 + jv*4 + 0];
            o.y = acc[i][jv*4+1] + bias[col0 + jv*4 + 1];
            o.z = acc[i][jv*4+2] + bias[col0 + jv*4 + 2];
            o.w = acc[i][jv*4+3] + bias[col0 + jv*4 + 3];
            if (relu) {
                o.x = fmaxf(o.x, 0.f); o.y = fmaxf(o.y, 0.f);
                o.z = fmaxf(o.z, 0.f); o.w = fmaxf(o.w, 0.f);
            }
            *(float4*)(C + row * N + col0 + jv * 4) = o;
        }
    }
#endif
}

// ---------------- embedding + sinusoidal PE ----------------
__global__ void __launch_bounds__(256)
embed_kernel(const int* __restrict__ ids, const float* __restrict__ emb,
             float* __restrict__ x)
{
    const int row = blockIdx.x;
    const int s   = row & (NS - 1);
    const int id  = ids[row];
    const float* er = emb + (size_t)id * ND;
    float* xr = x + (size_t)row * ND;
    const int tid = threadIdx.x;
#pragma unroll
    for (int i = 0; i < 4; i++) {
        int d  = tid + i * 256;
        int p2 = d & ~1;
        float freq = expf(-logf(10000.0f) * (float)p2 / (float)ND);
        float ang  = (float)s * freq;
        float pe   = (d & 1) ? cosf(ang) : sinf(ang);
        xr[d] = er[d] * 32.0f + pe;
    }
}

// ---------------- fused flash attention (vectorized LDS.128 inner loops) ----
// K stored transposed in smem (Kt[d][k]); Q/V/P row-major, rows padded to 68
// floats for 16B alignment. Identical FMA accumulation order to R5.
#define FA_STR 68
#define FA_SMEM (4 * 64 * FA_STR * 4)   // 69632 B

__global__ void __launch_bounds__(256)
flash_kernel(const float* __restrict__ q, const float* __restrict__ k,
             const float* __restrict__ v, const int* __restrict__ ids,
             float* __restrict__ ctx)
{
    extern __shared__ float fs[];
    float (*Qs)[FA_STR] = (float(*)[FA_STR])fs;
    float (*Kt)[FA_STR] = (float(*)[FA_STR])(fs + 64 * FA_STR);   // [d][k]
    float (*Vs)[FA_STR] = (float(*)[FA_STR])(fs + 2 * 64 * FA_STR);
    float (*Ps)[FA_STR] = (float(*)[FA_STR])(fs + 3 * 64 * FA_STR);
    __shared__ int idt[64];

    const int qt = blockIdx.x;
    const int bh = blockIdx.y;
    const int b = bh >> 4, h = bh & 15;
    const int q0 = qt * 64;
    const int tid = threadIdx.x;
    const int tr = tid >> 4, tc = tid & 15;

    const float* qb = q + (size_t)b * NS * ND + h * NHD;
    const float* kb = k + (size_t)b * NS * ND + h * NHD;
    const float* vb = v + (size_t)b * NS * ND + h * NHD;
    const int* idr = ids + b * NS;

    for (int i = tid; i < 64 * 16; i += 256) {
        int r = i >> 4, c = (i & 15) << 2;
        float4 t = *(const float4*)(qb + (size_t)(q0 + r) * ND + c);
        *(float4*)&Qs[r][c] = t;
    }

    float m[4], l[4], O[4][4];
#pragma unroll
    for (int i = 0; i < 4; i++) {
        m[i] = -INFINITY; l[i] = 0.f;
#pragma unroll
        for (int j = 0; j < 4; j++) O[i][j] = 0.f;
    }

    for (int kt = 0; kt <= qt; kt++) {
        __syncthreads();
        for (int i = tid; i < 64 * 16; i += 256) {
            int r = i >> 4, c = (i & 15) << 2;
            float4 t = *(const float4*)(kb + (size_t)(kt * 64 + r) * ND + c);
            Kt[c + 0][r] = t.x; Kt[c + 1][r] = t.y;       // transposed store
            Kt[c + 2][r] = t.z; Kt[c + 3][r] = t.w;
            float4 u = *(const float4*)(vb + (size_t)(kt * 64 + r) * ND + c);
            *(float4*)&Vs[r][c] = u;
        }
        if (tid < 64) idt[tid] = idr[kt * 64 + tid];
        __syncthreads();

        // S = Q K^T via vectorized loads (same FMA order as scalar version)
        float sc[4][4];
#pragma unroll
        for (int i = 0; i < 4; i++)
#pragma unroll
            for (int j = 0; j < 4; j++) sc[i][j] = 0.f;
#pragma unroll
        for (int d4 = 0; d4 < 64; d4 += 4) {
            float qv[4][4], kv[4][4];
#pragma unroll
            for (int i = 0; i < 4; i++) {
                float4 t = *(const float4*)&Qs[tr * 4 + i][d4];   // broadcast
                qv[i][0] = t.x; qv[i][1] = t.y; qv[i][2] = t.z; qv[i][3] = t.w;
            }
#pragma unroll
            for (int t2 = 0; t2 < 4; t2++) {
                float4 t = *(const float4*)&Kt[d4 + t2][tc * 4];  // contiguous k
                kv[t2][0] = t.x; kv[t2][1] = t.y; kv[t2][2] = t.z; kv[t2][3] = t.w;
            }
#pragma unroll
            for (int i = 0; i < 4; i++)
#pragma unroll
                for (int j = 0; j < 4; j++) {
                    sc[i][j] += qv[i][0] * kv[0][j];
                    sc[i][j] += qv[i][1] * kv[1][j];
                    sc[i][j] += qv[i][2] * kv[2][j];
                    sc[i][j] += qv[i][3] * kv[3][j];
                }
        }
#pragma unroll
        for (int i = 0; i < 4; i++) {
            int qq = q0 + tr * 4 + i;
#pragma unroll
            for (int j = 0; j < 4; j++) {
                int kk = kt * 64 + tc * 4 + j;
                bool masked = (kk > qq) || (idt[tc * 4 + j] == 0);
                sc[i][j] = masked ? -INFINITY : sc[i][j] * 0.125f;
            }
        }
#pragma unroll
        for (int i = 0; i < 4; i++) {
            float tmax = fmaxf(fmaxf(sc[i][0], sc[i][1]), fmaxf(sc[i][2], sc[i][3]));
#pragma unroll
            for (int o = 8; o > 0; o >>= 1)
                tmax = fmaxf(tmax, __shfl_xor_sync(0xffffffffu, tmax, o));
            float mn = fmaxf(m[i], tmax);
            float alpha = (m[i] == -INFINITY) ? 0.f : expf(m[i] - mn);
            float p0 = (sc[i][0] == -INFINITY) ? 0.f : expf(sc[i][0] - mn);
            float p1 = (sc[i][1] == -INFINITY) ? 0.f : expf(sc[i][1] - mn);
            float p2 = (sc[i][2] == -INFINITY) ? 0.f : expf(sc[i][2] - mn);
            float p3 = (sc[i][3] == -INFINITY) ? 0.f : expf(sc[i][3] - mn);
            float rsum = p0 + p1 + p2 + p3;
#pragma unroll
            for (int o = 8; o > 0; o >>= 1)
                rsum += __shfl_xor_sync(0xffffffffu, rsum, o);
            l[i] = l[i] * alpha + rsum;
            m[i] = mn;
            Ps[tr * 4 + i][tc * 4 + 0] = p0;
            Ps[tr * 4 + i][tc * 4 + 1] = p1;
            Ps[tr * 4 + i][tc * 4 + 2] = p2;
            Ps[tr * 4 + i][tc * 4 + 3] = p3;
#pragma unroll
            for (int j = 0; j < 4; j++) O[i][j] *= alpha;
        }
        __syncthreads();
        // O += P V (vectorized; same accumulation order over k)
#pragma unroll
        for (int k4 = 0; k4 < 64; k4 += 4) {
            float pv_[4][4], vv[4][4];
#pragma unroll
            for (int i = 0; i < 4; i++) {
                float4 t = *(const float4*)&Ps[tr * 4 + i][k4];   // broadcast
                pv_[i][0] = t.x; pv_[i][1] = t.y; pv_[i][2] = t.z; pv_[i][3] = t.w;
            }
#pragma unroll
            for (int t2 = 0; t2 < 4; t2++) {
                float4 t = *(const float4*)&Vs[k4 + t2][tc * 4];  // contiguous d
                vv[t2][0] = t.x; vv[t2][1] = t.y; vv[t2][2] = t.z; vv[t2][3] = t.w;
            }
#pragma unroll
            for (int i = 0; i < 4; i++)
#pragma unroll
                for (int j = 0; j < 4; j++) {
                    O[i][j] += pv_[i][0] * vv[0][j];
                    O[i][j] += pv_[i][1] * vv[1][j];
                    O[i][j] += pv_[i][2] * vv[2][j];
                    O[i][j] += pv_[i][3] * vv[3][j];
                }
        }
    }

#pragma unroll
    for (int i = 0; i < 4; i++) {
        int qq = q0 + tr * 4 + i;
        float4 o;
        if (m[i] == -INFINITY) {
            float s0 = 0.f, s1 = 0.f, s2 = 0.f, s3 = 0.f;
            for (int kk = 0; kk < NS; kk++) {
                const float* vr = vb + (size_t)kk * ND + tc * 4;
                s0 += vr[0]; s1 += vr[1]; s2 += vr[2]; s3 += vr[3];
            }
            o.x = s0 * (1.0f / NS); o.y = s1 * (1.0f / NS);
            o.z = s2 * (1.0f / NS); o.w = s3 * (1.0f / NS);
        } else {
            float inv = 1.0f / l[i];
            o.x = O[i][0] * inv; o.y = O[i][1] * inv;
            o.z = O[i][2] * inv; o.w = O[i][3] * inv;
        }
        *(float4*)(ctx + (size_t)(b * NS + qq) * ND + h * NHD + tc * 4) = o;
    }
}

// ---------------- x = LayerNorm(x + y) ----------------
__global__ void __launch_bounds__(256)
ln_kernel(float* __restrict__ x, const float* __restrict__ y,
          const float* __restrict__ g, const float* __restrict__ b)
{
    const int row = blockIdx.x;
    float* xr = x + (size_t)row * ND;
    const float* yr = y + (size_t)row * ND;
    const int tid = threadIdx.x;
    float4 xv = *(float4*)(xr + tid * 4);
    float4 yv = *(const float4*)(yr + tid * 4);
    float t0 = xv.x + yv.x, t1 = xv.y + yv.y, t2 = xv.z + yv.z, t3 = xv.w + yv.w;
    float s  = t0 + t1 + t2 + t3;
    float ss = t0*t0 + t1*t1 + t2*t2 + t3*t3;
#pragma unroll
    for (int o = 16; o > 0; o >>= 1) {
        s  += __shfl_xor_sync(0xffffffffu, s,  o);
        ss += __shfl_xor_sync(0xffffffffu, ss, o);
    }
    __shared__ float rs[8], rss[8];
    if ((tid & 31) == 0) { rs[tid >> 5] = s; rss[tid >> 5] = ss; }
    __syncthreads();
    float S = 0.f, SS = 0.f;
#pragma unroll
    for (int w = 0; w < 8; w++) { S += rs[w]; SS += rss[w]; }
    float mean = S * (1.0f / ND);
    float var  = SS * (1.0f / ND) - mean * mean;
    float rstd = rsqrtf(var + 1e-5f);
    float4 gv = *(const float4*)(g + tid * 4);
    float4 bv = *(const float4*)(b + tid * 4);
    float4 o;
    o.x = (t0 - mean) * rstd * gv.x + bv.x;
    o.y = (t1 - mean) * rstd * gv.y + bv.y;
    o.z = (t2 - mean) * rstd * gv.z + bv.z;
    o.w = (t3 - mean) * rstd * gv.w + bv.w;
    *(float4*)(xr + tid * 4) = o;
}

// ---------------- host orchestration (EXACT R5 schedule) --------------------
extern "C" void kernel_launch(void* const* d_in, const int* in_sizes, int n_in,
                              void* d_out, int out_size)
{
    const int*   ids  = (const int*)  d_in[0];
    const float* emb  = (const float*)d_in[2];
    const float* Wq   = (const float*)d_in[3];
    const float* bq   = (const float*)d_in[4];
    const float* Wk   = (const float*)d_in[5];
    const float* bk   = (const float*)d_in[6];
    const float* Wv   = (const float*)d_in[7];
    const float* bv   = (const float*)d_in[8];
    const float* Wo   = (const float*)d_in[9];
    const float* bo   = (const float*)d_in[10];
    const float* g1   = (const float*)d_in[11];
    const float* b1n  = (const float*)d_in[12];
    const float* W1   = (const float*)d_in[13];
    const float* b1f  = (const float*)d_in[14];
    const float* W2   = (const float*)d_in[15];
    const float* b2f  = (const float*)d_in[16];
    const float* g2   = (const float*)d_in[17];
    const float* b2n  = (const float*)d_in[18];
    const float* Wout = (const float*)d_in[19];
    const float* bout = (const float*)d_in[20];
    float* out = (float*)d_out;

    float *px, *pq, *pk, *pv, *pctx, *ptmp, *pff, *pwt;
    cudaGetSymbolAddress((void**)&px,   g_x);
    cudaGetSymbolAddress((void**)&pq,   g_q);
    cudaGetSymbolAddress((void**)&pk,   g_k);
    cudaGetSymbolAddress((void**)&pv,   g_v);
    cudaGetSymbolAddress((void**)&pctx, g_ctx);
    cudaGetSymbolAddress((void**)&ptmp, g_tmp);
    cudaGetSymbolAddress((void**)&pff,  g_ff);
    cudaGetSymbolAddress((void**)&pwt,  g_wt);

    cudaFuncSetAttribute(gemm_tc, cudaFuncAttributeMaxDynamicSharedMemorySize,
                         G_SMEM_BYTES);
    cudaFuncSetAttribute(flash_kernel, cudaFuncAttributeMaxDynamicSharedMemorySize,
                         FA_SMEM);

    embed_kernel<<<NT, 256>>>(ids, emb, px);

    const dim3 tDD(ND / 64, ND / 64);       // (16,16)
    const dim3 tDF(NF / 64, ND / 64);
    const dim3 tFD(ND / 64, NF / 64);
    const dim3 tDV(NV / 64, ND / 64);

    const dim3 gProj(NT / 128, ND / 128);   // (16, 8)
    const dim3 gFF1 (NT / 128, NF / 128);   // (16, 32)
    const dim3 gOut (NT / 128, NV / 128);   // (16, 250)
    const dim3 gFA  (NS / 64, NB * NH);     // (8, 64)

    for (int l = 0; l < NL; l++) {
        const float* wq = Wq + (size_t)l * ND * ND;
        const float* wk = Wk + (size_t)l * ND * ND;
        const float* wv = Wv + (size_t)l * ND * ND;
        const float* wo = Wo + (size_t)l * ND * ND;
        const float* w1 = W1 + (size_t)l * ND * NF;
        const float* w2 = W2 + (size_t)l * NF * ND;

        transpose_kernel<<<tDD, 256>>>(wq, pwt, ND, ND);
        gemm_tc<<<gProj, 256, G_SMEM_BYTES>>>(px, pwt, bq + l * ND, pq, NT, ND, ND, 0);
        transpose_kernel<<<tDD, 256>>>(wk, pwt, ND, ND);
        gemm_tc<<<gProj, 256, G_SMEM_BYTES>>>(px, pwt, bk + l * ND, pk, NT, ND, ND, 0);
        transpose_kernel<<<tDD, 256>>>(wv, pwt, ND, ND);
        gemm_tc<<<gProj, 256, G_SMEM_BYTES>>>(px, pwt, bv + l * ND, pv, NT, ND, ND, 0);

        flash_kernel<<<gFA, 256, FA_SMEM>>>(pq, pk, pv, ids, pctx);

        transpose_kernel<<<tDD, 256>>>(wo, pwt, ND, ND);
        gemm_tc<<<gProj, 256, G_SMEM_BYTES>>>(pctx, pwt, bo + l * ND, ptmp, NT, ND, ND, 0);
        ln_kernel<<<NT, 256>>>(px, ptmp, g1 + l * ND, b1n + l * ND);

        transpose_kernel<<<tDF, 256>>>(w1, pwt, ND, NF);
        gemm_tc<<<gFF1, 256, G_SMEM_BYTES>>>(px, pwt, b1f + l * NF, pff, NT, NF, ND, 1);
        transpose_kernel<<<tFD, 256>>>(w2, pwt, NF, ND);
        gemm_tc<<<gProj, 256, G_SMEM_BYTES>>>(pff, pwt, b2f + l * ND, ptmp, NT, ND, NF, 0);
        ln_kernel<<<NT, 256>>>(px, ptmp, g2 + l * ND, b2n + l * ND);
    }

    transpose_kernel<<<tDV, 256>>>(Wout, pwt, ND, NV);
    gemm_tc<<<gOut, 256, G_SMEM_BYTES>>>(px, pwt, bout, out, NT, NV, ND, 0);
}